// round 1
// baseline (speedup 1.0000x reference)
#include <cuda_runtime.h>
#include <cstdint>
#include <math.h>

// Problem constants
#define BB   128            // batch
#define TT   512            // timesteps
#define II   256            // input dim
#define HH   1024           // hidden dim
#define CC   1000           // classes
#define KKTOT (II + HH)     // 1280, GEMM K per step (A = [x_t | h])
#define NCTA 128
#define NTHR 256
#define HPC  8              // hidden columns owned per CTA (HH / NCTA)
#define NG   32             // gate columns per CTA (4 gates * HPC)
#define BK   32             // K tile

// Persistent state (device globals: no allocation allowed)
__device__ float    g_h[2][BB * HH];   // double-buffered hidden state
__device__ unsigned g_bar;             // grid barrier counter (reset each launch)
__device__ unsigned g_done;            // completion handshake

// Packed fp32x2 FMA (sm_100+): 2 MACs per FMA-pipe issue slot
__device__ __forceinline__ unsigned long long ffma2(unsigned long long a,
                                                    unsigned long long b,
                                                    unsigned long long c) {
    unsigned long long d;
    asm("fma.rn.f32x2 %0, %1, %2, %3;" : "=l"(d) : "l"(a), "l"(b), "l"(c));
    return d;
}

__device__ __forceinline__ void gbar(unsigned target) {
    __syncthreads();
    if (threadIdx.x == 0) {
        __threadfence();                     // release all prior writes to GPU scope
        atomicAdd(&g_bar, 1u);
        unsigned cur;
        do {
            asm volatile("ld.global.acquire.gpu.u32 %0, [%1];"
                         : "=r"(cur) : "l"(&g_bar) : "memory");
        } while (cur < target);
    }
    __syncthreads();
}

__device__ __forceinline__ float sigf(float x) { return 1.0f / (1.0f + expf(-x)); }

__global__ __launch_bounds__(NTHR, 1)
void lstm_persistent(const float* __restrict__ x,     // [B, T, I]
                     const float* __restrict__ W_ih,  // [4H, I]
                     const float* __restrict__ W_hh,  // [4H, H]
                     const float* __restrict__ b_ih,  // [4H]
                     const float* __restrict__ b_hh,  // [4H]
                     const float* __restrict__ fcW,   // [C, H]
                     const float* __restrict__ fcb,   // [C]
                     float* __restrict__ out)         // [B, C]
{
    // SMEM tiles (static, ~42.9 KB total)
    __shared__ __align__(16) float As[BB][BK + 2];   // A tile, m-major (pad even -> 8B aligned rows)
    __shared__ __align__(16) float Bs[NG][BK + 2];   // W tile, n-major
    __shared__ float Gs[BB][NG + 1];                 // gate pre-activations
    __shared__ float cs[BB][HPC];                    // resident cell state slice
    __shared__ float bias_s[NG];

    const int tid  = threadIdx.x;
    const int cta  = blockIdx.x;
    const int col0 = cta * HPC;          // first hidden column owned by this CTA
    const int tx   = tid & 7;            // output col group (4 cols)
    const int ty   = tid >> 3;           // output row group (4 rows)
    unsigned phase = 0;

    // ---- init: zero h read-buffer slice + cell state, load biases ----
#pragma unroll
    for (int r = 0; r < 4; r++) {
        int e = tid + r * NTHR;          // e in [0, 1024)
        int brow = e >> 3, j = e & 7;
        g_h[0][brow * HH + col0 + j] = 0.0f;
        cs[brow][j] = 0.0f;
    }
    if (tid < NG) {
        int wr = ((tid >> 3) << 10) + col0 + (tid & 7);   // gate*H + hcol
        bias_s[tid] = b_ih[wr] + b_hh[wr];
    }
    gbar(++phase * NCTA);

    // ---- sequential timestep loop ----
    for (int t = 0; t < TT; t++) {
        const float* hr = g_h[t & 1];           // read buffer
        float*       hw = g_h[(t & 1) ^ 1];     // write buffer

        unsigned long long acc[4][4];
#pragma unroll
        for (int i = 0; i < 4; i++)
#pragma unroll
            for (int j = 0; j < 4; j++) acc[i][j] = 0ull;

        for (int kt = 0; kt < KKTOT; kt += BK) {
            const bool  inx   = (kt < II);      // tile never straddles the x/h boundary (256 % 32 == 0)
            const float* Abase = inx ? (x + t * II + kt) : (hr + (kt - II));
            const int    Astr  = inx ? (TT * II) : HH;
            const float* Wbase = inx ? (W_ih + kt) : (W_hh + (kt - II));
            const int    Wstr  = inx ? II : HH;

            // A tile: 128x32, coalesced 32-float rows. __ldcg: h changes each
            // step and L1 is NOT coherent across CTAs -> must read from L2.
#pragma unroll
            for (int r = 0; r < 16; r++) {
                int e = tid + r * NTHR;
                int m = e >> 5, k = e & 31;
                As[m][k] = __ldcg(Abase + m * Astr + k);
            }
            // W tile: 32x32 (weights are immutable: let them live in L1 across steps)
#pragma unroll
            for (int r = 0; r < 4; r++) {
                int e = tid + r * NTHR;
                int n = e >> 5, k = e & 31;
                int wr = ((n >> 3) << 10) + col0 + (n & 7);
                Bs[n][k] = Wbase[wr * Wstr + k];
            }
            __syncthreads();

            // 4x4 register tile, K vectorized by 2 via fma.rn.f32x2
#pragma unroll
            for (int k2 = 0; k2 < BK / 2; k2++) {
                unsigned long long a2[4], b2[4];
#pragma unroll
                for (int i = 0; i < 4; i++)
                    a2[i] = *reinterpret_cast<const unsigned long long*>(&As[ty * 4 + i][k2 * 2]);
#pragma unroll
                for (int j = 0; j < 4; j++)
                    b2[j] = *reinterpret_cast<const unsigned long long*>(&Bs[tx * 4 + j][k2 * 2]);
#pragma unroll
                for (int i = 0; i < 4; i++)
#pragma unroll
                    for (int j = 0; j < 4; j++)
                        acc[i][j] = ffma2(a2[i], b2[j], acc[i][j]);
            }
            __syncthreads();
        }

        // epilogue: horizontal add of f32x2 lanes + bias -> Gs
#pragma unroll
        for (int i = 0; i < 4; i++)
#pragma unroll
            for (int j = 0; j < 4; j++) {
                float lo, hi;
                asm("mov.b64 {%0, %1}, %2;" : "=f"(lo), "=f"(hi) : "l"(acc[i][j]));
                Gs[ty * 4 + i][tx * 4 + j] = lo + hi + bias_s[tx * 4 + j];
            }
        __syncthreads();

        // elementwise LSTM cell update (PyTorch gate order i,f,g,o)
#pragma unroll
        for (int r = 0; r < 4; r++) {
            int e = tid + r * NTHR;              // e in [0, 1024)
            int brow = e >> 3, j = e & 7;
            float zi = Gs[brow][j];
            float zf = Gs[brow][8 + j];
            float zg = Gs[brow][16 + j];
            float zo = Gs[brow][24 + j];
            float cv = sigf(zf) * cs[brow][j] + sigf(zi) * tanhf(zg);
            cs[brow][j] = cv;
            hw[brow * HH + col0 + j] = sigf(zo) * tanhf(cv);
        }
        gbar(++phase * NCTA);   // all h writes visible before next step's reads
    }

    // ---- fused FC: out[b, c] = h_final . fcW[c] + fcb[c] ----
    const float* hfin = g_h[TT & 1];             // TT even -> buffer 0
#pragma unroll
    for (int r = 0; r < 4; r++) {
        int e = tid + r * NTHR;
        int brow = e >> 3, jc = e & 7;
        int col = col0 + jc;                     // CTA covers cols [cta*8, cta*8+8)
        if (col < CC) {
            const float4* hb = reinterpret_cast<const float4*>(hfin + brow * HH);
            const float4* wb = reinterpret_cast<const float4*>(fcW + col * HH);
            float a = 0.0f;
#pragma unroll 8
            for (int k4 = 0; k4 < HH / 4; k4++) {
                float4 hv = __ldcg(hb + k4);
                float4 wv = wb[k4];
                a += hv.x * wv.x + hv.y * wv.y + hv.z * wv.z + hv.w * wv.w;
            }
            out[brow * CC + col] = a + fcb[col];
        }
    }

    // ---- reset barrier state so graph replays are deterministic ----
    __syncthreads();
    if (tid == 0) {
        __threadfence();
        unsigned d = atomicAdd(&g_done, 1u);
        if (d == NCTA - 1) {          // last CTA: everyone is past all spins
            atomicExch(&g_bar, 0u);
            atomicExch(&g_done, 0u);
        }
    }
}

extern "C" void kernel_launch(void* const* d_in, const int* in_sizes, int n_in,
                              void* d_out, int out_size) {
    (void)in_sizes; (void)n_in; (void)out_size;
    const float* x    = (const float*)d_in[0];
    const float* W_ih = (const float*)d_in[1];
    const float* W_hh = (const float*)d_in[2];
    const float* b_ih = (const float*)d_in[3];
    const float* b_hh = (const float*)d_in[4];
    const float* fcW  = (const float*)d_in[5];
    const float* fcb  = (const float*)d_in[6];
    lstm_persistent<<<NCTA, NTHR>>>(x, W_ih, W_hh, b_ih, b_hh, fcW, fcb, (float*)d_out);
}

// round 2
// speedup vs baseline: 1.0021x; 1.0021x over previous
#include <cuda_runtime.h>
#include <cstdint>
#include <math.h>

// Problem constants
#define BB   128            // batch
#define TT   512            // timesteps
#define II   256            // input dim
#define HH   1024           // hidden dim
#define CC   1000           // classes
#define KKTOT (II + HH)     // 1280, GEMM K per step (A = [x_t | h])
#define NCTA 128
#define NTHR 256
#define HPC  8              // hidden columns owned per CTA (HH / NCTA)
#define NG   32             // gate columns per CTA (4 gates * HPC)
#define BK   32             // K tile

// Persistent state (device globals: no allocation allowed)
__device__ float    g_h[2][BB * HH];   // double-buffered hidden state
__device__ unsigned g_bar;             // grid barrier counter (reset each launch)
__device__ unsigned g_done;            // completion handshake

// Packed fp32x2 FMA (sm_100+): 2 MACs per FMA-pipe issue slot
__device__ __forceinline__ unsigned long long ffma2(unsigned long long a,
                                                    unsigned long long b,
                                                    unsigned long long c) {
    unsigned long long d;
    asm("fma.rn.f32x2 %0, %1, %2, %3;" : "=l"(d) : "l"(a), "l"(b), "l"(c));
    return d;
}

__device__ __forceinline__ void gbar(unsigned target) {
    __syncthreads();
    if (threadIdx.x == 0) {
        __threadfence();                     // release all prior writes to GPU scope
        atomicAdd(&g_bar, 1u);
        unsigned cur;
        do {
            asm volatile("ld.global.acquire.gpu.u32 %0, [%1];"
                         : "=r"(cur) : "l"(&g_bar) : "memory");
        } while (cur < target);
    }
    __syncthreads();
}

__device__ __forceinline__ float sigf(float x) { return 1.0f / (1.0f + expf(-x)); }

__global__ __launch_bounds__(NTHR, 1)
void lstm_persistent(const float* __restrict__ x,     // [B, T, I]
                     const float* __restrict__ W_ih,  // [4H, I]
                     const float* __restrict__ W_hh,  // [4H, H]
                     const float* __restrict__ b_ih,  // [4H]
                     const float* __restrict__ b_hh,  // [4H]
                     const float* __restrict__ fcW,   // [C, H]
                     const float* __restrict__ fcb,   // [C]
                     float* __restrict__ out)         // [B, C]
{
    // SMEM tiles (static, ~42.9 KB total)
    __shared__ __align__(16) float As[BB][BK + 2];   // A tile, m-major (pad even -> 8B aligned rows)
    __shared__ __align__(16) float Bs[NG][BK + 2];   // W tile, n-major
    __shared__ float Gs[BB][NG + 1];                 // gate pre-activations
    __shared__ float cs[BB][HPC];                    // resident cell state slice
    __shared__ float bias_s[NG];

    const int tid  = threadIdx.x;
    const int cta  = blockIdx.x;
    const int col0 = cta * HPC;          // first hidden column owned by this CTA
    const int tx   = tid & 7;            // output col group (4 cols)
    const int ty   = tid >> 3;           // output row group (4 rows)
    unsigned phase = 0;

    // ---- init: zero h read-buffer slice + cell state, load biases ----
#pragma unroll
    for (int r = 0; r < 4; r++) {
        int e = tid + r * NTHR;          // e in [0, 1024)
        int brow = e >> 3, j = e & 7;
        g_h[0][brow * HH + col0 + j] = 0.0f;
        cs[brow][j] = 0.0f;
    }
    if (tid < NG) {
        int wr = ((tid >> 3) << 10) + col0 + (tid & 7);   // gate*H + hcol
        bias_s[tid] = b_ih[wr] + b_hh[wr];
    }
    gbar(++phase * NCTA);

    // ---- sequential timestep loop ----
    for (int t = 0; t < TT; t++) {
        const float* hr = g_h[t & 1];           // read buffer
        float*       hw = g_h[(t & 1) ^ 1];     // write buffer

        unsigned long long acc[4][4];
#pragma unroll
        for (int i = 0; i < 4; i++)
#pragma unroll
            for (int j = 0; j < 4; j++) acc[i][j] = 0ull;

        for (int kt = 0; kt < KKTOT; kt += BK) {
            const bool  inx   = (kt < II);      // tile never straddles the x/h boundary (256 % 32 == 0)
            const float* Abase = inx ? (x + t * II + kt) : (hr + (kt - II));
            const int    Astr  = inx ? (TT * II) : HH;
            const float* Wbase = inx ? (W_ih + kt) : (W_hh + (kt - II));
            const int    Wstr  = inx ? II : HH;

            // A tile: 128x32, coalesced 32-float rows. __ldcg: h changes each
            // step and L1 is NOT coherent across CTAs -> must read from L2.
#pragma unroll
            for (int r = 0; r < 16; r++) {
                int e = tid + r * NTHR;
                int m = e >> 5, k = e & 31;
                As[m][k] = __ldcg(Abase + m * Astr + k);
            }
            // W tile: 32x32 (weights are immutable: let them live in L1 across steps)
#pragma unroll
            for (int r = 0; r < 4; r++) {
                int e = tid + r * NTHR;
                int n = e >> 5, k = e & 31;
                int wr = ((n >> 3) << 10) + col0 + (n & 7);
                Bs[n][k] = Wbase[wr * Wstr + k];
            }
            __syncthreads();

            // 4x4 register tile, K vectorized by 2 via fma.rn.f32x2
#pragma unroll
            for (int k2 = 0; k2 < BK / 2; k2++) {
                unsigned long long a2[4], b2[4];
#pragma unroll
                for (int i = 0; i < 4; i++)
                    a2[i] = *reinterpret_cast<const unsigned long long*>(&As[ty * 4 + i][k2 * 2]);
#pragma unroll
                for (int j = 0; j < 4; j++)
                    b2[j] = *reinterpret_cast<const unsigned long long*>(&Bs[tx * 4 + j][k2 * 2]);
#pragma unroll
                for (int i = 0; i < 4; i++)
#pragma unroll
                    for (int j = 0; j < 4; j++)
                        acc[i][j] = ffma2(a2[i], b2[j], acc[i][j]);
            }
            __syncthreads();
        }

        // epilogue: horizontal add of f32x2 lanes + bias -> Gs
#pragma unroll
        for (int i = 0; i < 4; i++)
#pragma unroll
            for (int j = 0; j < 4; j++) {
                float lo, hi;
                asm("mov.b64 {%0, %1}, %2;" : "=f"(lo), "=f"(hi) : "l"(acc[i][j]));
                Gs[ty * 4 + i][tx * 4 + j] = lo + hi + bias_s[tx * 4 + j];
            }
        __syncthreads();

        // elementwise LSTM cell update (PyTorch gate order i,f,g,o)
#pragma unroll
        for (int r = 0; r < 4; r++) {
            int e = tid + r * NTHR;              // e in [0, 1024)
            int brow = e >> 3, j = e & 7;
            float zi = Gs[brow][j];
            float zf = Gs[brow][8 + j];
            float zg = Gs[brow][16 + j];
            float zo = Gs[brow][24 + j];
            float cv = sigf(zf) * cs[brow][j] + sigf(zi) * tanhf(zg);
            cs[brow][j] = cv;
            hw[brow * HH + col0 + j] = sigf(zo) * tanhf(cv);
        }
        gbar(++phase * NCTA);   // all h writes visible before next step's reads
    }

    // ---- fused FC: out[b, c] = h_final . fcW[c] + fcb[c] ----
    const float* hfin = g_h[TT & 1];             // TT even -> buffer 0
#pragma unroll
    for (int r = 0; r < 4; r++) {
        int e = tid + r * NTHR;
        int brow = e >> 3, jc = e & 7;
        int col = col0 + jc;                     // CTA covers cols [cta*8, cta*8+8)
        if (col < CC) {
            const float4* hb = reinterpret_cast<const float4*>(hfin + brow * HH);
            const float4* wb = reinterpret_cast<const float4*>(fcW + col * HH);
            float a = 0.0f;
#pragma unroll 8
            for (int k4 = 0; k4 < HH / 4; k4++) {
                float4 hv = __ldcg(hb + k4);
                float4 wv = wb[k4];
                a += hv.x * wv.x + hv.y * wv.y + hv.z * wv.z + hv.w * wv.w;
            }
            out[brow * CC + col] = a + fcb[col];
        }
    }

    // ---- reset barrier state so graph replays are deterministic ----
    __syncthreads();
    if (tid == 0) {
        __threadfence();
        unsigned d = atomicAdd(&g_done, 1u);
        if (d == NCTA - 1) {          // last CTA: everyone is past all spins
            atomicExch(&g_bar, 0u);
            atomicExch(&g_done, 0u);
        }
    }
}

extern "C" void kernel_launch(void* const* d_in, const int* in_sizes, int n_in,
                              void* d_out, int out_size) {
    (void)in_sizes; (void)n_in; (void)out_size;
    const float* x    = (const float*)d_in[0];
    const float* W_ih = (const float*)d_in[1];
    const float* W_hh = (const float*)d_in[2];
    const float* b_ih = (const float*)d_in[3];
    const float* b_hh = (const float*)d_in[4];
    const float* fcW  = (const float*)d_in[5];
    const float* fcb  = (const float*)d_in[6];
    lstm_persistent<<<NCTA, NTHR>>>(x, W_ih, W_hh, b_ih, b_hh, fcW, fcb, (float*)d_out);
}